// round 1
// baseline (speedup 1.0000x reference)
#include <cuda_runtime.h>

// HistogramLayer inference:
//   hist_probs[b,d] = freq[b,d] / sum_b freq[b,d]
//   bin[r,d] = clip(searchsorted_right(edges[:,d], x[r,d]) - 1, 0, 7)
//   out[r] = prod_d hist_probs[bin[r,d], d]
//
// Edges are uniform per feature (linspace(-4,4,9)*scale[d]), so the bin is
// guessed arithmetically (1 FMA + F2I) and then verified/corrected against the
// REAL edge values so boundary semantics match searchsorted exactly.

#define HD 16   // features
#define HNB 8   // bins

__global__ __launch_bounds__(256)
void HistogramLayer_13048110645959_kernel(
    const float* __restrict__ inputs,   // [B, 16]
    const float* __restrict__ freq,     // [8, 16]
    const float* __restrict__ edges,    // [9, 16]
    float* __restrict__ out,            // [B]
    int B)
{
    // Per-(d,bin) cell: {e_lo, e_hi, prob, pad}. 16B aligned -> LDS.128.
    // For a fixed d, the 8 bins occupy 8 disjoint 4-bank groups (8*16B = 128B),
    // and identical bins broadcast -> conflict-free data-dependent gather.
    __shared__ float4 tab[HD * HNB];     // 2 KB
    __shared__ float  s_inv[HD];         // 1/scale per feature

    const int tid = threadIdx.x;

    if (tid < HD * HNB) {
        const int d = tid >> 3;
        const int b = tid & 7;
        float s = 0.f;
        #pragma unroll
        for (int k = 0; k < HNB; ++k) s += freq[k * HD + d];
        const float p  = freq[b * HD + d] / s;
        const float lo = edges[b * HD + d];
        const float hi = edges[(b + 1) * HD + d];
        tab[d * HNB + b] = make_float4(lo, hi, p, 0.f);
    }
    if (tid < HD) {
        // edges[8,d] = 4 * scale[d] exactly (mult by 4 is exact in fp32)
        const float scale = edges[8 * HD + tid] * 0.25f;
        s_inv[tid] = 1.0f / scale;
    }
    __syncthreads();

    const int row = blockIdx.x * blockDim.x + tid;
    if (row >= B) return;

    // 4 x LDG.128 per row, issued back-to-back for MLP.
    const float4* in4 = reinterpret_cast<const float4*>(inputs + (size_t)row * HD);
    const float4 v0 = in4[0];
    const float4 v1 = in4[1];
    const float4 v2 = in4[2];
    const float4 v3 = in4[3];

    float x[HD];
    x[0]=v0.x; x[1]=v0.y; x[2]=v0.z; x[3]=v0.w;
    x[4]=v1.x; x[5]=v1.y; x[6]=v1.z; x[7]=v1.w;
    x[8]=v2.x; x[9]=v2.y; x[10]=v2.z; x[11]=v2.w;
    x[12]=v3.x; x[13]=v3.y; x[14]=v3.z; x[15]=v3.w;

    float prod = 1.0f;
    #pragma unroll
    for (int d = 0; d < HD; ++d) {
        const float xv = x[d];
        // Arithmetic guess: t = x/scale + 4 -> floor -> clamp.
        const float t = fmaf(xv, s_inv[d], 4.0f);
        int b = __float2int_rd(t);
        b = max(0, min(HNB - 1, b));

        float4 c = tab[d * HNB + b];

        // Exact correction against the real edges (searchsorted side="right"):
        // want e[b] <= x < e[b+1] with clamping at the ends.
        int b2 = b + ((xv >= c.y) ? 1 : 0) - ((xv < c.x) ? 1 : 0);
        b2 = max(0, min(HNB - 1, b2));
        if (b2 != b) c = tab[d * HNB + b2];   // rare (fp rounding near an edge)

        prod *= c.z;
    }

    out[row] = prod;
}

extern "C" void kernel_launch(void* const* d_in, const int* in_sizes, int n_in,
                              void* d_out, int out_size)
{
    // Identify tensors by element count (robust to metadata ordering):
    //   inputs: B*16 (large), frequencies: 8*16=128, edges: 9*16=144.
    const float* inputs = nullptr;
    const float* freq   = nullptr;
    const float* edges  = nullptr;
    int B = 0;
    for (int i = 0; i < n_in; ++i) {
        if (in_sizes[i] == HNB * HD)            freq   = (const float*)d_in[i];
        else if (in_sizes[i] == (HNB + 1) * HD) edges  = (const float*)d_in[i];
        else { inputs = (const float*)d_in[i];  B = in_sizes[i] / HD; }
    }

    float* out = (float*)d_out;
    const int threads = 256;
    const int blocks = (B + threads - 1) / threads;
    HistogramLayer_13048110645959_kernel<<<blocks, threads>>>(inputs, freq, edges, out, B);
}

// round 2
// speedup vs baseline: 2.1957x; 2.1957x over previous
#include <cuda_runtime.h>

// HistogramLayer inference:
//   hist_probs[b,d] = freq[b,d] / sum_b freq[b,d]
//   bin[r,d] = clip(searchsorted_right(edges[:,d], x[r,d]) - 1, 0, 7)
//   out[r] = prod_d hist_probs[bin[r,d], d]
//
// Edges are linspace(-4,4,9)[b] * scale[d] with integer base points, so
// edge[b][d] = round((b-4)*scale_d): a single fp32 rounding that we reproduce
// bit-exactly in registers via fmaf(float(b), s, -4s), where -4s = -edges[8][d]
// exactly. The shared table therefore only holds probabilities (LDS.32 gather,
// 8 distinct banks per warp -> conflict-free, 1 phase).

#define HD 16   // features
#define HNB 8   // bins

__global__ __launch_bounds__(256)
void HistogramLayer_13048110645959_kernel(
    const float* __restrict__ inputs,   // [B, 16]
    const float* __restrict__ freq,     // [8, 16]
    const float* __restrict__ edges,    // [9, 16]
    float* __restrict__ out,            // [B]
    int B)
{
    __shared__ float  s_prob[HD * HNB];   // [d][b] probabilities, 512 B
    __shared__ float4 s_c[HD];            // per-feature (scale, -4*scale, 1/scale, 0)

    const int tid = threadIdx.x;

    if (tid < HD * HNB) {
        const int d = tid >> 3;
        const int b = tid & 7;
        float s = 0.f;
        #pragma unroll
        for (int k = 0; k < HNB; ++k) s += freq[k * HD + d];
        s_prob[d * HNB + b] = freq[b * HD + d] / s;
    }
    if (tid < HD) {
        const float e8    = edges[8 * HD + tid]; // = 4*scale exactly
        const float scale = e8 * 0.25f;          // exact
        s_c[tid] = make_float4(scale, -e8, 1.0f / scale, 0.f);
    }
    __syncthreads();

    const int row = blockIdx.x * blockDim.x + tid;
    if (row >= B) return;

    // 4 x LDG.128 per row, front-batched for MLP.
    const float4* in4 = reinterpret_cast<const float4*>(inputs + (size_t)row * HD);
    const float4 v0 = in4[0];
    const float4 v1 = in4[1];
    const float4 v2 = in4[2];
    const float4 v3 = in4[3];

    float x[HD];
    x[0]=v0.x; x[1]=v0.y; x[2]=v0.z; x[3]=v0.w;
    x[4]=v1.x; x[5]=v1.y; x[6]=v1.z; x[7]=v1.w;
    x[8]=v2.x; x[9]=v2.y; x[10]=v2.z; x[11]=v2.w;
    x[12]=v3.x; x[13]=v3.y; x[14]=v3.z; x[15]=v3.w;

    float prod0 = 1.0f, prod1 = 1.0f;   // two chains to halve FMUL dep depth
    #pragma unroll
    for (int d = 0; d < HD; ++d) {
        const float  xv = x[d];
        const float4 c  = s_c[d];            // broadcast LDS.128

        // Arithmetic guess: floor(x/scale + 4), clamped.
        int b = __float2int_rd(fmaf(xv, c.z, 4.0f));
        b = max(0, min(HNB - 1, b));

        // Exact edges in registers (bit-identical to reference):
        //   e_lo = round(b*s - 4s), e_hi = round((b+1)*s - 4s)
        const float fb   = (float)b;
        const float e_lo = fmaf(fb,        c.x, c.y);
        const float e_hi = fmaf(fb + 1.0f, c.x, c.y);

        // searchsorted(side="right") correction, then clamp.
        b += ((xv >= e_hi) ? 1 : 0) - ((xv < e_lo) ? 1 : 0);
        b = max(0, min(HNB - 1, b));

        const float p = s_prob[d * HNB + b]; // LDS.32, conflict-free
        if (d & 1) prod1 *= p; else prod0 *= p;
    }

    out[row] = prod0 * prod1;
}

extern "C" void kernel_launch(void* const* d_in, const int* in_sizes, int n_in,
                              void* d_out, int out_size)
{
    // Identify tensors by element count:
    //   inputs: B*16 (large), frequencies: 8*16=128, edges: 9*16=144.
    const float* inputs = nullptr;
    const float* freq   = nullptr;
    const float* edges  = nullptr;
    int B = 0;
    for (int i = 0; i < n_in; ++i) {
        if (in_sizes[i] == HNB * HD)            freq   = (const float*)d_in[i];
        else if (in_sizes[i] == (HNB + 1) * HD) edges  = (const float*)d_in[i];
        else { inputs = (const float*)d_in[i];  B = in_sizes[i] / HD; }
    }

    float* out = (float*)d_out;
    const int threads = 256;
    const int blocks = (B + threads - 1) / threads;
    HistogramLayer_13048110645959_kernel<<<blocks, threads>>>(inputs, freq, edges, out, B);
}

// round 3
// speedup vs baseline: 2.7801x; 1.2662x over previous
#include <cuda_runtime.h>

// HistogramLayer inference:
//   hist_probs[b,d] = freq[b,d] / sum_b freq[b,d]
//   bin[r,d] = clip(searchsorted_right(edges[:,d], x[r,d]) - 1, 0, 7)
//   out[r] = prod_d hist_probs[bin[r,d], d]
//
// Edges are base[b]*scale[d] with base = -4..4 integers, so
// edge[b][d] = round((b-4)*scale_d). Since edges[8][d] = 4*scale exactly,
// ((b-4)*0.25f) is exact and one FMUL by e8 reproduces the reference edge
// bit-exactly. Bin = arithmetic guess (FMA + F2I) + exact +-1 correction
// against the real rounded edges. Probabilities are gathered pairwise from a
// 2KB shared table of p[2p][b0]*p[2p+1][b1].

#define HD  16   // features
#define HNB 8    // bins
#define RPT 8    // rows per thread

__device__ __forceinline__ int find_bin(float xv, float inv, float e8)
{
    // guess: floor(x/scale + 4)
    const float t = fmaf(xv, inv, 4.0f);
    int b = __float2int_rd(t);
    const float fb = (float)b;
    const float u  = fmaf(fb, 0.25f, -1.0f);   // (b-4)/4, exact
    const float elo = u * e8;                  // == reference edge[b]
    const float ehi = (u + 0.25f) * e8;        // == reference edge[b+1]
    // x >= ehi  -> +1 ; x < elo -> -1  (sign-bit arithmetic; x==edge -> +0)
    const int shi = (int)(__float_as_uint(xv - ehi) >> 31); // 1 iff x < ehi
    const int slo = (int)(__float_as_uint(xv - elo) >> 31); // 1 iff x < elo
    b += 1 - shi - slo;
    return max(0, min(HNB - 1, b));
}

__global__ __launch_bounds__(256)
void HistogramLayer_13048110645959_kernel(
    const float* __restrict__ inputs,   // [B, 16]
    const float* __restrict__ freq,     // [8, 16]
    const float* __restrict__ edges,    // [9, 16]
    float* __restrict__ out,            // [B]
    int B)
{
    __shared__ float s_prob[HD * HNB];        // [d][b]
    __shared__ float s_pair[(HD / 2) * 64];   // [pair][b0][b1], 2 KB

    const int tid = threadIdx.x;

    // stage 1: normalized probabilities
    if (tid < HD * HNB) {
        const int d = tid >> 3;
        const int b = tid & 7;
        float s = 0.f;
        #pragma unroll
        for (int k = 0; k < HNB; ++k) s += freq[k * HD + d];
        s_prob[d * HNB + b] = freq[b * HD + d] / s;
    }
    __syncthreads();
    // stage 2: pairwise products
    #pragma unroll
    for (int i = tid; i < (HD / 2) * 64; i += 256) {
        const int p  = i >> 6;
        const int b0 = (i >> 3) & 7;
        const int b1 = i & 7;
        s_pair[i] = s_prob[(2 * p) * HNB + b0] * s_prob[(2 * p + 1) * HNB + b1];
    }
    __syncthreads();

    // per-feature constants in registers (uniform loads, L1-resident)
    float e8[HD], inv[HD];
    #pragma unroll
    for (int d = 0; d < HD; ++d) {
        e8[d]  = edges[8 * HD + d];            // = 4*scale exactly
        inv[d] = __fdividef(4.0f, e8[d]);      // ~1/scale (errors corrected)
    }

    const int base = blockIdx.x * (256 * RPT) + tid;

    #pragma unroll
    for (int r = 0; r < RPT; ++r) {
        const int row = base + r * 256;
        if (row >= B) break;

        const float4* in4 = reinterpret_cast<const float4*>(inputs + (size_t)row * HD);
        const float4 v0 = in4[0];
        const float4 v1 = in4[1];
        const float4 v2 = in4[2];
        const float4 v3 = in4[3];

        float x[HD];
        x[0]=v0.x;  x[1]=v0.y;  x[2]=v0.z;  x[3]=v0.w;
        x[4]=v1.x;  x[5]=v1.y;  x[6]=v1.z;  x[7]=v1.w;
        x[8]=v2.x;  x[9]=v2.y;  x[10]=v2.z; x[11]=v2.w;
        x[12]=v3.x; x[13]=v3.y; x[14]=v3.z; x[15]=v3.w;

        float prod0 = 1.0f, prod1 = 1.0f;
        #pragma unroll
        for (int p = 0; p < HD / 2; ++p) {
            const int d0 = 2 * p, d1 = 2 * p + 1;
            const int b0 = find_bin(x[d0], inv[d0], e8[d0]);
            const int b1 = find_bin(x[d1], inv[d1], e8[d1]);
            const float pp = s_pair[(p << 6) + (b0 << 3) + b1];
            if (p & 1) prod1 *= pp; else prod0 *= pp;
        }
        out[row] = prod0 * prod1;
    }
}

extern "C" void kernel_launch(void* const* d_in, const int* in_sizes, int n_in,
                              void* d_out, int out_size)
{
    // Identify tensors by element count:
    //   inputs: B*16 (large), frequencies: 8*16=128, edges: 9*16=144.
    const float* inputs = nullptr;
    const float* freq   = nullptr;
    const float* edges  = nullptr;
    int B = 0;
    for (int i = 0; i < n_in; ++i) {
        if (in_sizes[i] == HNB * HD)            freq   = (const float*)d_in[i];
        else if (in_sizes[i] == (HNB + 1) * HD) edges  = (const float*)d_in[i];
        else { inputs = (const float*)d_in[i];  B = in_sizes[i] / HD; }
    }

    float* out = (float*)d_out;
    const int rows_per_block = 256 * RPT;
    const int blocks = (B + rows_per_block - 1) / rows_per_block;
    HistogramLayer_13048110645959_kernel<<<blocks, 256>>>(inputs, freq, edges, out, B);
}